// round 2
// baseline (speedup 1.0000x reference)
#include <cuda_runtime.h>
#include <math.h>

// Problem constants (fixed by setup_inputs)
#define NB 8
#define ND 60
#define NP 1024
#define NK 20
#define NT (NP*NK)          // 20480 edge-columns per (b, channel)
#define SLOPE 0.2f

// ---------------- device scratch (no cudaMalloc allowed) ----------------
static __device__ float dg_pd[NB*NP*NP];          // 32 MB pairwise -dist^2
static __device__ int   dg_idx[NB*NP*NK];
static __device__ float dg_P[NB*64*NP];           // w1[:, :60]  . x
static __device__ float dg_S[NB*64*NP];           // (w1[:,60:]-w1[:,:60]) . x
static __device__ float dg_h1[NB*64*NT];          // raw conv outputs (pre-BN)
static __device__ float dg_h2[NB*64*NT];
static __device__ float dg_h3[NB*128*NT];
static __device__ float dg_h4[NB*256*NT];
static __device__ float dg_z [NB*512*NP];         // raw maxes concat [x1|x2|x3|x4]
static __device__ float dg_o5[NB*256*NP];
static __device__ float dg_o6[NB*1024*NP];
static __device__ double dg_sum[6][1024];
static __device__ double dg_ssq[6][1024];
static __device__ float dg_scZ[512], dg_shZ[512];
static __device__ float dg_sc5[256], dg_sh5[256];
static __device__ float dg_sc6[1024], dg_sh6[1024];

// ---------------- kernels ----------------

__global__ void k_zero() {
    int i = blockIdx.x*1024 + threadIdx.x;      // 6*1024 launches
    ((double*)dg_sum)[i] = 0.0;
    ((double*)dg_ssq)[i] = 0.0;
}

// pairwise pd[b,n,m] = -||x_n - x_m||^2, tiled 32x32
__global__ void k_pdist(const float* __restrict__ x) {
    __shared__ float xn[ND][32], xm[ND][32];
    int b = blockIdx.z;
    int n0 = blockIdx.y*32, m0 = blockIdx.x*32;
    int tid = threadIdx.y*32 + threadIdx.x;
    for (int e = tid; e < ND*32; e += 1024) {
        int d = e >> 5, c = e & 31;
        size_t base = ((size_t)b*ND + d)*NP;
        xn[d][c] = x[base + n0 + c];
        xm[d][c] = x[base + m0 + c];
    }
    __syncthreads();
    float s = 0.f;
    #pragma unroll
    for (int d = 0; d < ND; d++) {
        float df = xn[d][threadIdx.y] - xm[d][threadIdx.x];
        s = fmaf(df, -df, s);
    }
    dg_pd[((size_t)b*NP + n0 + threadIdx.y)*NP + m0 + threadIdx.x] = s;
}

// per row: 20 iterative argmax (lower index wins ties -> matches jax top_k set)
__global__ void k_topk() {
    __shared__ float sv[NP];
    __shared__ float rv[256];
    __shared__ int   ri[256];
    int b = blockIdx.y, n = blockIdx.x, tid = threadIdx.x;
    const float* row = dg_pd + ((size_t)b*NP + n)*NP;
    for (int i = tid; i < NP; i += 256) sv[i] = row[i];
    __syncthreads();
    int* outp = dg_idx + ((size_t)b*NP + n)*NK;
    for (int t = 0; t < NK; t++) {
        float best = -INFINITY; int bi = NP;
        for (int i = tid; i < NP; i += 256) {
            float v = sv[i];
            if (v > best) { best = v; bi = i; }   // strided set is index-increasing
        }
        rv[tid] = best; ri[tid] = bi;
        __syncthreads();
        for (int s = 128; s > 0; s >>= 1) {
            if (tid < s) {
                float ov = rv[tid+s]; int oi = ri[tid+s];
                if (ov > rv[tid] || (ov == rv[tid] && oi < ri[tid])) { rv[tid] = ov; ri[tid] = oi; }
            }
            __syncthreads();
        }
        if (tid == 0) { outp[t] = ri[0]; sv[ri[0]] = -INFINITY; }
        __syncthreads();
    }
}

// P[b,o,n] = w1a . x[:,n],  S[b,o,n] = (w1b - w1a) . x[:,n]
__global__ void k_ps(const float* __restrict__ x, const float* __restrict__ w1) {
    __shared__ float wa[ND], ws[ND];
    int o = blockIdx.y, b = blockIdx.z, tid = threadIdx.x;
    if (tid < ND) {
        float a = w1[o*120 + tid];
        wa[tid] = a;
        ws[tid] = w1[o*120 + 60 + tid] - a;
    }
    __syncthreads();
    int n = blockIdx.x*256 + tid;
    float p = 0.f, s = 0.f;
    #pragma unroll
    for (int d = 0; d < ND; d++) {
        float xv = x[((size_t)b*ND + d)*NP + n];
        p = fmaf(wa[d], xv, p);
        s = fmaf(ws[d], xv, s);
    }
    dg_P[((size_t)b*64 + o)*NP + n] = p;
    dg_S[((size_t)b*64 + o)*NP + n] = s;
}

// conv1 as gather: h1[b,o,n,j] = P[b,o,idx[n,j]] + S[b,o,n] + b1[o]
__global__ void k_h1(const float* __restrict__ b1) {
    int tid = threadIdx.x;
    int n = blockIdx.x*256 + tid;
    int o = blockIdx.y, b = blockIdx.z;
    float sv = dg_S[((size_t)b*64 + o)*NP + n] + b1[o];
    const float* Pb = dg_P + ((size_t)b*64 + o)*NP;
    const int* ip = dg_idx + ((size_t)b*NP + n)*NK;
    float vals[NK];
    #pragma unroll
    for (int j = 0; j < NK; j++) vals[j] = Pb[ip[j]] + sv;
    float* dst = dg_h1 + (((size_t)b*64 + o)*NP + n)*NK;
    #pragma unroll
    for (int j4 = 0; j4 < 5; j4++)
        ((float4*)dst)[j4] = make_float4(vals[4*j4], vals[4*j4+1], vals[4*j4+2], vals[4*j4+3]);
}

// stats + max-over-k; raw maxes go straight into dg_z at channel offset zoff
__global__ void k_stats20(const float* __restrict__ raw, int C, int stage, int zoff) {
    int c = blockIdx.x, b = blockIdx.y, tid = threadIdx.x;
    const float* p = raw + ((size_t)b*C + c)*NT;
    float sum = 0.f, ss = 0.f;
    for (int n = tid; n < NP; n += 256) {
        const float4* q = (const float4*)(p + (size_t)n*NK);
        float mx = -INFINITY;
        #pragma unroll
        for (int j = 0; j < 5; j++) {
            float4 v = q[j];
            sum += v.x + v.y + v.z + v.w;
            ss = fmaf(v.x, v.x, ss); ss = fmaf(v.y, v.y, ss);
            ss = fmaf(v.z, v.z, ss); ss = fmaf(v.w, v.w, ss);
            mx = fmaxf(mx, fmaxf(fmaxf(v.x, v.y), fmaxf(v.z, v.w)));
        }
        dg_z[((size_t)b*512 + zoff + c)*NP + n] = mx;
    }
    __shared__ float s1[256], s2[256];
    s1[tid] = sum; s2[tid] = ss;
    __syncthreads();
    for (int s = 128; s > 0; s >>= 1) {
        if (tid < s) { s1[tid] += s1[tid+s]; s2[tid] += s2[tid+s]; }
        __syncthreads();
    }
    if (tid == 0) {
        atomicAdd(&dg_sum[stage][c], (double)s1[0]);
        atomicAdd(&dg_ssq[stage][c], (double)s2[0]);
    }
}

__global__ void k_stats1(const float* __restrict__ raw, int C, int stage) {
    int c = blockIdx.x, b = blockIdx.y, tid = threadIdx.x;
    const float* p = raw + ((size_t)b*C + c)*NP;
    float sum = 0.f, ss = 0.f;
    for (int n = tid; n < NP; n += 256) {
        float v = p[n];
        sum += v;
        ss = fmaf(v, v, ss);
    }
    __shared__ float s1[256], s2[256];
    s1[tid] = sum; s2[tid] = ss;
    __syncthreads();
    for (int s = 128; s > 0; s >>= 1) {
        if (tid < s) { s1[tid] += s1[tid+s]; s2[tid] += s2[tid+s]; }
        __syncthreads();
    }
    if (tid == 0) {
        atomicAdd(&dg_sum[stage][c], (double)s1[0]);
        atomicAdd(&dg_ssq[stage][c], (double)s2[0]);
    }
}

// (sum, sumsq) -> affine (scale, shift) so bn+act = lrelu(v*scale + shift)
__global__ void k_finalize(int stage, int C, float cnt,
                           const float* __restrict__ g, const float* __restrict__ be,
                           float* __restrict__ sc, float* __restrict__ sh) {
    int c = threadIdx.x;
    if (c < C) {
        double mu  = dg_sum[stage][c] / (double)cnt;
        double var = dg_ssq[stage][c] / (double)cnt - mu*mu;
        float scale = g[c] * (float)(1.0 / sqrt(var + 1e-5));
        sc[c] = scale;
        sh[c] = be[c] - (float)mu * scale;
    }
}

// SGEMM: Out[b,M,T] = W[M,K] x lrelu(A[b,K,T]*sc + sh) + bias
// 64x64 block tile, K-tile 16, 16x16 threads, 4x4 per thread
__global__ void k_gemm(const float* __restrict__ A, const float* __restrict__ W,
                       const float* __restrict__ bias,
                       const float* __restrict__ sc, const float* __restrict__ sh,
                       float* __restrict__ Out, int M, int K, int Tc) {
    __shared__ float As[16][64];
    __shared__ float Ws[16][65];
    int b = blockIdx.z;
    const float* Ab = A + (size_t)b*K*Tc;
    float* Ob = Out + (size_t)b*M*Tc;
    int m0 = blockIdx.y*64, t0 = blockIdx.x*64;
    int tx = threadIdx.x, ty = threadIdx.y;
    int tid = ty*16 + tx;
    float acc[4][4] = {};
    for (int k0 = 0; k0 < K; k0 += 16) {
        #pragma unroll
        for (int i = 0; i < 4; i++) {
            int e = tid + i*256;
            int r = e >> 6, c = e & 63;
            float v = Ab[(size_t)(k0+r)*Tc + t0 + c];
            v = fmaf(v, sc[k0+r], sh[k0+r]);
            As[r][c] = v >= 0.f ? v : SLOPE*v;
        }
        #pragma unroll
        for (int i = 0; i < 4; i++) {
            int e = tid + i*256;
            int r = e >> 4, c = e & 15;
            Ws[c][r] = W[(size_t)(m0+r)*K + k0 + c];
        }
        __syncthreads();
        #pragma unroll
        for (int kk = 0; kk < 16; kk++) {
            float4 a4 = *reinterpret_cast<const float4*>(&As[kk][tx*4]);
            float av[4] = {a4.x, a4.y, a4.z, a4.w};
            float wv[4] = {Ws[kk][ty*4+0], Ws[kk][ty*4+1], Ws[kk][ty*4+2], Ws[kk][ty*4+3]};
            #pragma unroll
            for (int i = 0; i < 4; i++)
                #pragma unroll
                for (int j = 0; j < 4; j++)
                    acc[i][j] = fmaf(wv[i], av[j], acc[i][j]);
        }
        __syncthreads();
    }
    #pragma unroll
    for (int i = 0; i < 4; i++) {
        int m = m0 + ty*4 + i;
        float bv = bias[m];
        float4 o = make_float4(acc[i][0]+bv, acc[i][1]+bv, acc[i][2]+bv, acc[i][3]+bv);
        *reinterpret_cast<float4*>(&Ob[(size_t)m*Tc + t0 + tx*4]) = o;
    }
}

// final bn+lrelu + (B,C,N) -> (B,N,C) transpose
__global__ void k_out(float* __restrict__ out) {
    __shared__ float st[32][33];
    int b = blockIdx.z;
    int c0 = blockIdx.y*32, n0 = blockIdx.x*32;
    int tx = threadIdx.x, ty = threadIdx.y;
    int c = c0 + ty;
    float v = dg_o6[((size_t)b*1024 + c)*NP + n0 + tx];
    v = fmaf(v, dg_sc6[c], dg_sh6[c]);
    st[ty][tx] = v >= 0.f ? v : SLOPE*v;
    __syncthreads();
    out[((size_t)b*NP + n0 + ty)*1024 + c0 + tx] = st[tx][ty];
}

// ---------------- host orchestration ----------------

extern "C" void kernel_launch(void* const* d_in, const int* in_sizes, int n_in,
                              void* d_out, int out_size) {
    (void)in_sizes; (void)n_in; (void)out_size;
    const float* x  = (const float*)d_in[0];
    const float* w1 = (const float*)d_in[1];
    const float* b1 = (const float*)d_in[2];
    const float* g1 = (const float*)d_in[3];
    const float* be1= (const float*)d_in[4];
    const float* w2 = (const float*)d_in[5];
    const float* b2 = (const float*)d_in[6];
    const float* g2 = (const float*)d_in[7];
    const float* be2= (const float*)d_in[8];
    const float* w3 = (const float*)d_in[9];
    const float* b3 = (const float*)d_in[10];
    const float* g3 = (const float*)d_in[11];
    const float* be3= (const float*)d_in[12];
    const float* w4 = (const float*)d_in[13];
    const float* b4 = (const float*)d_in[14];
    const float* g4 = (const float*)d_in[15];
    const float* be4= (const float*)d_in[16];
    const float* w5 = (const float*)d_in[17];
    const float* b5 = (const float*)d_in[18];
    const float* g5 = (const float*)d_in[19];
    const float* be5= (const float*)d_in[20];
    const float* w6 = (const float*)d_in[21];
    const float* b6 = (const float*)d_in[22];
    const float* g6 = (const float*)d_in[23];
    const float* be6= (const float*)d_in[24];

    float *p_h1, *p_h2, *p_h3, *p_h4, *p_z, *p_o5, *p_o6;
    float *p_scZ, *p_shZ, *p_sc5, *p_sh5, *p_sc6, *p_sh6;
    cudaGetSymbolAddress((void**)&p_h1, dg_h1);
    cudaGetSymbolAddress((void**)&p_h2, dg_h2);
    cudaGetSymbolAddress((void**)&p_h3, dg_h3);
    cudaGetSymbolAddress((void**)&p_h4, dg_h4);
    cudaGetSymbolAddress((void**)&p_z,  dg_z);
    cudaGetSymbolAddress((void**)&p_o5, dg_o5);
    cudaGetSymbolAddress((void**)&p_o6, dg_o6);
    cudaGetSymbolAddress((void**)&p_scZ, dg_scZ);
    cudaGetSymbolAddress((void**)&p_shZ, dg_shZ);
    cudaGetSymbolAddress((void**)&p_sc5, dg_sc5);
    cudaGetSymbolAddress((void**)&p_sh5, dg_sh5);
    cudaGetSymbolAddress((void**)&p_sc6, dg_sc6);
    cudaGetSymbolAddress((void**)&p_sh6, dg_sh6);

    const float cntE = (float)(NB*NP*NK);  // 163840
    const float cntP = (float)(NB*NP);     // 8192

    k_zero<<<6, 1024>>>();
    k_pdist<<<dim3(NP/32, NP/32, NB), dim3(32, 32)>>>(x);
    k_topk<<<dim3(NP, NB), 256>>>();
    k_ps<<<dim3(NP/256, 64, NB), 256>>>(x, w1);
    k_h1<<<dim3(NP/256, 64, NB), 256>>>(b1);

    // stage1 stats/max -> z[0:64)
    k_stats20<<<dim3(64, NB), 256>>>(p_h1, 64, 0, 0);
    k_finalize<<<1, 64>>>(0, 64, cntE, g1, be1, p_scZ, p_shZ);

    // conv2: 64 <- 64 over 20480 edge-cols
    k_gemm<<<dim3(NT/64, 1, NB), dim3(16, 16)>>>(p_h1, w2, b2, p_scZ, p_shZ, p_h2, 64, 64, NT);
    k_stats20<<<dim3(64, NB), 256>>>(p_h2, 64, 1, 64);
    k_finalize<<<1, 64>>>(1, 64, cntE, g2, be2, p_scZ + 64, p_shZ + 64);

    // conv3: 128 <- 64
    k_gemm<<<dim3(NT/64, 2, NB), dim3(16, 16)>>>(p_h2, w3, b3, p_scZ + 64, p_shZ + 64, p_h3, 128, 64, NT);
    k_stats20<<<dim3(128, NB), 256>>>(p_h3, 128, 2, 128);
    k_finalize<<<1, 128>>>(2, 128, cntE, g3, be3, p_scZ + 128, p_shZ + 128);

    // conv4: 256 <- 128
    k_gemm<<<dim3(NT/64, 4, NB), dim3(16, 16)>>>(p_h3, w4, b4, p_scZ + 128, p_shZ + 128, p_h4, 256, 128, NT);
    k_stats20<<<dim3(256, NB), 256>>>(p_h4, 256, 3, 256);
    k_finalize<<<1, 256>>>(3, 256, cntE, g4, be4, p_scZ + 256, p_shZ + 256);

    // conv5: 256 <- 512 over N cols (z holds raw maxes; scZ/shZ normalize on load)
    k_gemm<<<dim3(NP/64, 4, NB), dim3(16, 16)>>>(p_z, w5, b5, p_scZ, p_shZ, p_o5, 256, 512, NP);
    k_stats1<<<dim3(256, NB), 256>>>(p_o5, 256, 4);
    k_finalize<<<1, 256>>>(4, 256, cntP, g5, be5, p_sc5, p_sh5);

    // conv6: 1024 <- 256
    k_gemm<<<dim3(NP/64, 16, NB), dim3(16, 16)>>>(p_o5, w6, b6, p_sc5, p_sh5, p_o6, 1024, 256, NP);
    k_stats1<<<dim3(1024, NB), 256>>>(p_o6, 1024, 5);
    k_finalize<<<1, 1024>>>(5, 1024, cntP, g6, be6, p_sc6, p_sh6);

    k_out<<<dim3(NP/32, 1024/32, NB), dim3(32, 32)>>>((float*)d_out);
}

// round 3
// speedup vs baseline: 1.2652x; 1.2652x over previous
#include <cuda_runtime.h>
#include <math.h>

// Problem constants (fixed by setup_inputs)
#define NB 8
#define ND 60
#define NP 1024
#define NK 20
#define NT (NP*NK)          // 20480 edge-columns per (b, channel)
#define SLOPE 0.2f

// ---------------- device scratch (no cudaMalloc allowed) ----------------
static __device__ float dg_pd[NB*NP*NP];          // pairwise -dist^2
static __device__ int   dg_idx[NB*NP*NK];
static __device__ float dg_P[NB*64*NP];           // w1[:, :60]  . x
static __device__ float dg_S[NB*64*NP];           // (w1[:,60:]-w1[:,:60]) . x
static __device__ float dg_h1[NB*64*NT];          // raw conv outputs (pre-BN)
static __device__ float dg_h2[NB*64*NT];
static __device__ float dg_h3[NB*128*NT];
static __device__ float dg_z [NB*512*NP];         // raw maxes concat [x1|x2|x3|x4]
static __device__ float dg_o5[NB*256*NP];
static __device__ float dg_o6[NB*1024*NP];
static __device__ double dg_sum[6][1024];
static __device__ double dg_ssq[6][1024];
static __device__ float dg_scZ[512], dg_shZ[512];
static __device__ float dg_sc5[256], dg_sh5[256];
static __device__ float dg_sc6[1024], dg_sh6[1024];

// packed fp32x2 FMA (sm_103a FFMA2) — exact fp32 numerics, 2x rate
#define FMA2(d, a, bb) asm("fma.rn.f32x2 %0, %1, %2, %0;" : "+l"(d) : "l"(a), "l"(bb))
#define DUP2(d, f)     asm("mov.b64 %0, {%1, %1};" : "=l"(d) : "f"(f))
#define UNPK2(lo, hi, d) asm("mov.b64 {%0, %1}, %2;" : "=f"(lo), "=f"(hi) : "l"(d))

// ---------------- kernels ----------------

__global__ void k_zero() {
    int i = blockIdx.x*1024 + threadIdx.x;
    ((double*)dg_sum)[i] = 0.0;
    ((double*)dg_ssq)[i] = 0.0;
}

// pairwise pd[b,n,m] = -||x_n - x_m||^2, tiled 32x32
__global__ void k_pdist(const float* __restrict__ x) {
    __shared__ float xn[ND][32], xm[ND][32];
    int b = blockIdx.z;
    int n0 = blockIdx.y*32, m0 = blockIdx.x*32;
    int tid = threadIdx.y*32 + threadIdx.x;
    for (int e = tid; e < ND*32; e += 1024) {
        int d = e >> 5, c = e & 31;
        size_t base = ((size_t)b*ND + d)*NP;
        xn[d][c] = x[base + n0 + c];
        xm[d][c] = x[base + m0 + c];
    }
    __syncthreads();
    float s = 0.f;
    #pragma unroll
    for (int d = 0; d < ND; d++) {
        float df = xn[d][threadIdx.y] - xm[d][threadIdx.x];
        s = fmaf(df, -df, s);
    }
    dg_pd[((size_t)b*NP + n0 + threadIdx.y)*NP + m0 + threadIdx.x] = s;
}

// per row: 20 iterative argmax (lower index wins ties -> matches jax top_k set)
__global__ void k_topk() {
    __shared__ float sv[NP];
    __shared__ float rv[256];
    __shared__ int   ri[256];
    int b = blockIdx.y, n = blockIdx.x, tid = threadIdx.x;
    const float* row = dg_pd + ((size_t)b*NP + n)*NP;
    for (int i = tid; i < NP; i += 256) sv[i] = row[i];
    __syncthreads();
    int* outp = dg_idx + ((size_t)b*NP + n)*NK;
    for (int t = 0; t < NK; t++) {
        float best = -INFINITY; int bi = NP;
        for (int i = tid; i < NP; i += 256) {
            float v = sv[i];
            if (v > best) { best = v; bi = i; }
        }
        rv[tid] = best; ri[tid] = bi;
        __syncthreads();
        for (int s = 128; s > 0; s >>= 1) {
            if (tid < s) {
                float ov = rv[tid+s]; int oi = ri[tid+s];
                if (ov > rv[tid] || (ov == rv[tid] && oi < ri[tid])) { rv[tid] = ov; ri[tid] = oi; }
            }
            __syncthreads();
        }
        if (tid == 0) { outp[t] = ri[0]; sv[ri[0]] = -INFINITY; }
        __syncthreads();
    }
}

// P[b,o,n] = w1a . x[:,n],  S[b,o,n] = (w1b - w1a) . x[:,n]
__global__ void k_ps(const float* __restrict__ x, const float* __restrict__ w1) {
    __shared__ float wa[ND], ws[ND];
    int o = blockIdx.y, b = blockIdx.z, tid = threadIdx.x;
    if (tid < ND) {
        float a = w1[o*120 + tid];
        wa[tid] = a;
        ws[tid] = w1[o*120 + 60 + tid] - a;
    }
    __syncthreads();
    int n = blockIdx.x*256 + tid;
    float p = 0.f, s = 0.f;
    #pragma unroll
    for (int d = 0; d < ND; d++) {
        float xv = x[((size_t)b*ND + d)*NP + n];
        p = fmaf(wa[d], xv, p);
        s = fmaf(ws[d], xv, s);
    }
    dg_P[((size_t)b*64 + o)*NP + n] = p;
    dg_S[((size_t)b*64 + o)*NP + n] = s;
}

// conv1 as gather + fused stats(stage0) + max -> z[0:64)
__global__ void k_h1(const float* __restrict__ b1) {
    int tid = threadIdx.x;
    int n = blockIdx.x*256 + tid;
    int o = blockIdx.y, b = blockIdx.z;
    float sv = dg_S[((size_t)b*64 + o)*NP + n] + b1[o];
    const float* Pb = dg_P + ((size_t)b*64 + o)*NP;
    const int* ip = dg_idx + ((size_t)b*NP + n)*NK;
    float vals[NK];
    float sum = 0.f, ss = 0.f, mx = -INFINITY;
    #pragma unroll
    for (int j = 0; j < NK; j++) {
        float v = Pb[ip[j]] + sv;
        vals[j] = v;
        sum += v;
        ss = fmaf(v, v, ss);
        mx = fmaxf(mx, v);
    }
    float* dst = dg_h1 + (((size_t)b*64 + o)*NP + n)*NK;
    #pragma unroll
    for (int j4 = 0; j4 < 5; j4++)
        ((float4*)dst)[j4] = make_float4(vals[4*j4], vals[4*j4+1], vals[4*j4+2], vals[4*j4+3]);
    dg_z[((size_t)b*512 + o)*NP + n] = mx;

    __shared__ float s1[256], s2[256];
    s1[tid] = sum; s2[tid] = ss;
    __syncthreads();
    for (int s = 128; s > 0; s >>= 1) {
        if (tid < s) { s1[tid] += s1[tid+s]; s2[tid] += s2[tid+s]; }
        __syncthreads();
    }
    if (tid == 0) {
        atomicAdd(&dg_sum[0][o], (double)s1[0]);
        atomicAdd(&dg_ssq[0][o], (double)s2[0]);
    }
}

// (sum, sumsq) -> affine (scale, shift) so bn+act = lrelu(v*scale + shift)
__global__ void k_finalize(int stage, int C, float cnt,
                           const float* __restrict__ g, const float* __restrict__ be,
                           float* __restrict__ sc, float* __restrict__ sh) {
    int c = threadIdx.x;
    if (c < C) {
        double mu  = dg_sum[stage][c] / (double)cnt;
        double var = dg_ssq[stage][c] / (double)cnt - mu*mu;
        float scale = g[c] * (float)(1.0 / sqrt(var + 1e-5));
        sc[c] = scale;
        sh[c] = be[c] - (float)mu * scale;
    }
}

// ================= edge-domain SGEMM (FFMA2) with fused stats + max =========
// Out[b,M,NT] = W[M,K] x lrelu(A*sc+sh) + bias.  Tile 64m x 160t (= 8 points),
// 256 threads, per-thread 4m x 5 f32x2-pairs. Epilogue: per-point max (no
// atomics) -> dg_z, per-channel sum/ssq -> double atomics. WRITE=false skips
// storing the output tensor entirely (conv4).
template<bool WRITE>
__global__ void __launch_bounds__(256) k_egemm(
        const float* __restrict__ A, const float* __restrict__ W,
        const float* __restrict__ bias,
        const float* __restrict__ sc, const float* __restrict__ sh,
        float* __restrict__ Out, int M, int K, int stage, int zoff) {
    __shared__ float As[16][160];
    __shared__ float Ws[16][68];
    int b = blockIdx.z;
    const float* Ab = A + (size_t)b*K*NT;
    int m0 = blockIdx.y*64, t0 = blockIdx.x*160;
    int tid = threadIdx.x;
    int tx = tid & 15, ty = tid >> 4;
    unsigned long long acc[4][5];
    #pragma unroll
    for (int i = 0; i < 4; i++)
        #pragma unroll
        for (int q = 0; q < 5; q++) acc[i][q] = 0ull;

    for (int k0 = 0; k0 < K; k0 += 16) {
        // A tile: 16 x 160 floats = 640 float4
        #pragma unroll
        for (int e = tid; e < 640; e += 256) {
            int r = e / 40, c = (e % 40) * 4;
            float4 v = *(const float4*)(Ab + (size_t)(k0+r)*NT + t0 + c);
            float s = sc[k0+r], h = sh[k0+r];
            v.x = fmaf(v.x, s, h); v.x = v.x >= 0.f ? v.x : SLOPE*v.x;
            v.y = fmaf(v.y, s, h); v.y = v.y >= 0.f ? v.y : SLOPE*v.y;
            v.z = fmaf(v.z, s, h); v.z = v.z >= 0.f ? v.z : SLOPE*v.z;
            v.w = fmaf(v.w, s, h); v.w = v.w >= 0.f ? v.w : SLOPE*v.w;
            *(float4*)&As[r][c] = v;
        }
        // W tile: 64 x 16, stored transposed
        {
            int r = tid >> 2, c = (tid & 3) * 4;
            float4 w = *(const float4*)(W + (size_t)(m0+r)*K + k0 + c);
            Ws[c+0][r] = w.x; Ws[c+1][r] = w.y; Ws[c+2][r] = w.z; Ws[c+3][r] = w.w;
        }
        __syncthreads();
        #pragma unroll
        for (int kk = 0; kk < 16; kk++) {
            const unsigned long long* arow =
                (const unsigned long long*)&As[kk][tx*10];
            unsigned long long ap[5];
            #pragma unroll
            for (int q = 0; q < 5; q++) ap[q] = arow[q];
            float4 wf = *(const float4*)&Ws[kk][ty*4];
            float wv[4] = {wf.x, wf.y, wf.z, wf.w};
            #pragma unroll
            for (int i = 0; i < 4; i++) {
                unsigned long long wp;
                DUP2(wp, wv[i]);
                #pragma unroll
                for (int q = 0; q < 5; q++) FMA2(acc[i][q], ap[q], wp);
            }
        }
        __syncthreads();
    }

    float* Ob = WRITE ? (Out + (size_t)b*M*NT) : (float*)0;
    #pragma unroll
    for (int i = 0; i < 4; i++) {
        int m = m0 + ty*4 + i;
        float bv = bias[m];
        float sum = 0.f, ss = 0.f, mxv = -INFINITY;
        #pragma unroll
        for (int q = 0; q < 5; q++) {
            float lo, hi;
            UNPK2(lo, hi, acc[i][q]);
            lo += bv; hi += bv;
            if (WRITE)
                *(float2*)(Ob + (size_t)m*NT + t0 + tx*10 + 2*q) = make_float2(lo, hi);
            sum += lo + hi;
            ss = fmaf(lo, lo, ss); ss = fmaf(hi, hi, ss);
            mxv = fmaxf(mxv, fmaxf(lo, hi));
        }
        #pragma unroll
        for (int d = 1; d < 16; d <<= 1) {
            sum += __shfl_xor_sync(0xffffffffu, sum, d);
            ss  += __shfl_xor_sync(0xffffffffu, ss, d);
        }
        if (tx == 0) {
            atomicAdd(&dg_sum[stage][m], (double)sum);
            atomicAdd(&dg_ssq[stage][m], (double)ss);
        }
        // two lanes (tx=2p, 2p+1) together cover the 20 j's of point p
        float mo = fmaxf(mxv, __shfl_xor_sync(0xffffffffu, mxv, 1));
        if ((tx & 1) == 0)
            dg_z[((size_t)b*512 + zoff + m)*NP + blockIdx.x*8 + (tx >> 1)] = mo;
    }
}

// ================= point-domain SGEMM (FFMA2) with fused stats ==============
// Tile 64m x 128t, per-thread 4m x 4 f32x2-pairs, pair columns 2tx+32q.
__global__ void __launch_bounds__(256) k_pgemm(
        const float* __restrict__ A, const float* __restrict__ W,
        const float* __restrict__ bias,
        const float* __restrict__ sc, const float* __restrict__ sh,
        float* __restrict__ Out, int M, int K, int stage) {
    __shared__ float As[16][128];
    __shared__ float Ws[16][68];
    int b = blockIdx.z;
    const float* Ab = A + (size_t)b*K*NP;
    float* Ob = Out + (size_t)b*M*NP;
    int m0 = blockIdx.y*64, t0 = blockIdx.x*128;
    int tid = threadIdx.x;
    int tx = tid & 15, ty = tid >> 4;
    unsigned long long acc[4][4];
    #pragma unroll
    for (int i = 0; i < 4; i++)
        #pragma unroll
        for (int q = 0; q < 4; q++) acc[i][q] = 0ull;

    for (int k0 = 0; k0 < K; k0 += 16) {
        #pragma unroll
        for (int e = tid; e < 512; e += 256) {
            int r = e >> 5, c = (e & 31) * 4;
            float4 v = *(const float4*)(Ab + (size_t)(k0+r)*NP + t0 + c);
            float s = sc[k0+r], h = sh[k0+r];
            v.x = fmaf(v.x, s, h); v.x = v.x >= 0.f ? v.x : SLOPE*v.x;
            v.y = fmaf(v.y, s, h); v.y = v.y >= 0.f ? v.y : SLOPE*v.y;
            v.z = fmaf(v.z, s, h); v.z = v.z >= 0.f ? v.z : SLOPE*v.z;
            v.w = fmaf(v.w, s, h); v.w = v.w >= 0.f ? v.w : SLOPE*v.w;
            *(float4*)&As[r][c] = v;
        }
        {
            int r = tid >> 2, c = (tid & 3) * 4;
            float4 w = *(const float4*)(W + (size_t)(m0+r)*K + k0 + c);
            Ws[c+0][r] = w.x; Ws[c+1][r] = w.y; Ws[c+2][r] = w.z; Ws[c+3][r] = w.w;
        }
        __syncthreads();
        #pragma unroll
        for (int kk = 0; kk < 16; kk++) {
            const unsigned long long* arow = (const unsigned long long*)&As[kk][0];
            unsigned long long ap[4];
            #pragma unroll
            for (int q = 0; q < 4; q++) ap[q] = arow[tx + 16*q];
            float4 wf = *(const float4*)&Ws[kk][ty*4];
            float wv[4] = {wf.x, wf.y, wf.z, wf.w};
            #pragma unroll
            for (int i = 0; i < 4; i++) {
                unsigned long long wp;
                DUP2(wp, wv[i]);
                #pragma unroll
                for (int q = 0; q < 4; q++) FMA2(acc[i][q], ap[q], wp);
            }
        }
        __syncthreads();
    }

    #pragma unroll
    for (int i = 0; i < 4; i++) {
        int m = m0 + ty*4 + i;
        float bv = bias[m];
        float sum = 0.f, ss = 0.f;
        #pragma unroll
        for (int q = 0; q < 4; q++) {
            float lo, hi;
            UNPK2(lo, hi, acc[i][q]);
            lo += bv; hi += bv;
            *(float2*)(Ob + (size_t)m*NP + t0 + 2*tx + 32*q) = make_float2(lo, hi);
            sum += lo + hi;
            ss = fmaf(lo, lo, ss); ss = fmaf(hi, hi, ss);
        }
        #pragma unroll
        for (int d = 1; d < 16; d <<= 1) {
            sum += __shfl_xor_sync(0xffffffffu, sum, d);
            ss  += __shfl_xor_sync(0xffffffffu, ss, d);
        }
        if (tx == 0) {
            atomicAdd(&dg_sum[stage][m], (double)sum);
            atomicAdd(&dg_ssq[stage][m], (double)ss);
        }
    }
}

// final bn+lrelu + (B,C,N) -> (B,N,C) transpose
__global__ void k_out(float* __restrict__ out) {
    __shared__ float st[32][33];
    int b = blockIdx.z;
    int c0 = blockIdx.y*32, n0 = blockIdx.x*32;
    int tx = threadIdx.x, ty = threadIdx.y;
    int c = c0 + ty;
    float v = dg_o6[((size_t)b*1024 + c)*NP + n0 + tx];
    v = fmaf(v, dg_sc6[c], dg_sh6[c]);
    st[ty][tx] = v >= 0.f ? v : SLOPE*v;
    __syncthreads();
    out[((size_t)b*NP + n0 + ty)*1024 + c0 + tx] = st[tx][ty];
}

// ---------------- host orchestration ----------------

extern "C" void kernel_launch(void* const* d_in, const int* in_sizes, int n_in,
                              void* d_out, int out_size) {
    (void)in_sizes; (void)n_in; (void)out_size;
    const float* x  = (const float*)d_in[0];
    const float* w1 = (const float*)d_in[1];
    const float* b1 = (const float*)d_in[2];
    const float* g1 = (const float*)d_in[3];
    const float* be1= (const float*)d_in[4];
    const float* w2 = (const float*)d_in[5];
    const float* b2 = (const float*)d_in[6];
    const float* g2 = (const float*)d_in[7];
    const float* be2= (const float*)d_in[8];
    const float* w3 = (const float*)d_in[9];
    const float* b3 = (const float*)d_in[10];
    const float* g3 = (const float*)d_in[11];
    const float* be3= (const float*)d_in[12];
    const float* w4 = (const float*)d_in[13];
    const float* b4 = (const float*)d_in[14];
    const float* g4 = (const float*)d_in[15];
    const float* be4= (const float*)d_in[16];
    const float* w5 = (const float*)d_in[17];
    const float* b5 = (const float*)d_in[18];
    const float* g5 = (const float*)d_in[19];
    const float* be5= (const float*)d_in[20];
    const float* w6 = (const float*)d_in[21];
    const float* b6 = (const float*)d_in[22];
    const float* g6 = (const float*)d_in[23];
    const float* be6= (const float*)d_in[24];

    float *p_h1, *p_h2, *p_h3, *p_z, *p_o5, *p_o6;
    float *p_scZ, *p_shZ, *p_sc5, *p_sh5, *p_sc6, *p_sh6;
    cudaGetSymbolAddress((void**)&p_h1, dg_h1);
    cudaGetSymbolAddress((void**)&p_h2, dg_h2);
    cudaGetSymbolAddress((void**)&p_h3, dg_h3);
    cudaGetSymbolAddress((void**)&p_z,  dg_z);
    cudaGetSymbolAddress((void**)&p_o5, dg_o5);
    cudaGetSymbolAddress((void**)&p_o6, dg_o6);
    cudaGetSymbolAddress((void**)&p_scZ, dg_scZ);
    cudaGetSymbolAddress((void**)&p_shZ, dg_shZ);
    cudaGetSymbolAddress((void**)&p_sc5, dg_sc5);
    cudaGetSymbolAddress((void**)&p_sh5, dg_sh5);
    cudaGetSymbolAddress((void**)&p_sc6, dg_sc6);
    cudaGetSymbolAddress((void**)&p_sh6, dg_sh6);

    const float cntE = (float)(NB*NP*NK);  // 163840
    const float cntP = (float)(NB*NP);     // 8192

    k_zero<<<6, 1024>>>();
    k_pdist<<<dim3(NP/32, NP/32, NB), dim3(32, 32)>>>(x);
    k_topk<<<dim3(NP, NB), 256>>>();
    k_ps<<<dim3(NP/256, 64, NB), 256>>>(x, w1);

    // conv1 (gather) + fused stats0 + max -> z[0:64)
    k_h1<<<dim3(NP/256, 64, NB), 256>>>(b1);
    k_finalize<<<1, 64>>>(0, 64, cntE, g1, be1, p_scZ, p_shZ);

    // conv2: 64 <- 64, writes h2 + stats1 + max -> z[64:128)
    k_egemm<true><<<dim3(NT/160, 1, NB), 256>>>(p_h1, w2, b2, p_scZ, p_shZ, p_h2, 64, 64, 1, 64);
    k_finalize<<<1, 64>>>(1, 64, cntE, g2, be2, p_scZ + 64, p_shZ + 64);

    // conv3: 128 <- 64, writes h3 + stats2 + max -> z[128:256)
    k_egemm<true><<<dim3(NT/160, 2, NB), 256>>>(p_h2, w3, b3, p_scZ + 64, p_shZ + 64, p_h3, 128, 64, 2, 128);
    k_finalize<<<1, 128>>>(2, 128, cntE, g3, be3, p_scZ + 128, p_shZ + 128);

    // conv4: 256 <- 128, NO output tensor — only stats3 + max -> z[256:512)
    k_egemm<false><<<dim3(NT/160, 4, NB), 256>>>(p_h3, w4, b4, p_scZ + 128, p_shZ + 128, (float*)0, 256, 128, 3, 256);
    k_finalize<<<1, 256>>>(3, 256, cntE, g4, be4, p_scZ + 256, p_shZ + 256);

    // conv5: 256 <- 512 over points (z normalized on load) + stats4
    k_pgemm<<<dim3(NP/128, 4, NB), 256>>>(p_z, w5, b5, p_scZ, p_shZ, p_o5, 256, 512, 4);
    k_finalize<<<1, 256>>>(4, 256, cntP, g5, be5, p_sc5, p_sh5);

    // conv6: 1024 <- 256 + stats5
    k_pgemm<<<dim3(NP/128, 16, NB), 256>>>(p_o5, w6, b6, p_sc5, p_sh5, p_o6, 1024, 256, 5);
    k_finalize<<<1, 1024>>>(5, 1024, cntP, g6, be6, p_sc6, p_sh6);

    k_out<<<dim3(NP/32, 1024/32, NB), dim3(32, 32)>>>((float*)d_out);
}

// round 4
// speedup vs baseline: 1.8166x; 1.4358x over previous
#include <cuda_runtime.h>
#include <math.h>

#define NB 8
#define ND 60
#define NP 1024
#define NK 20
#define NT (NP*NK)
#define SLOPE 0.2f

typedef unsigned long long ull;

// ---------------- device scratch ----------------
static __device__ float dg_pd[NB*NP*NP];
static __device__ float dg_xx[NB*NP];
static __device__ int   dg_idx[NB*NP*NK];
static __device__ float dg_P[NB*64*NP];
static __device__ float dg_S[NB*64*NP];
static __device__ float dg_h1[NB*64*NT];
static __device__ float dg_h2[NB*64*NT];
static __device__ float dg_h3[NB*128*NT];
static __device__ float dg_z [NB*512*NP];
static __device__ float dg_o5[NB*256*NP];
static __device__ float dg_o6[NB*1024*NP];
static __device__ double dg_sum[6][1024];
static __device__ double dg_ssq[6][1024];
static __device__ float dg_scZ[512], dg_shZ[512];
static __device__ float dg_sc5[256], dg_sh5[256];
static __device__ float dg_sc6[1024], dg_sh6[1024];

// packed fp32x2 FMA (sm_103a) — exact fp32 numerics per lane, 2x rate
#define FMA2(d, a, bb) asm("fma.rn.f32x2 %0, %1, %2, %0;" : "+l"(d) : "l"(a), "l"(bb))
#define DUP2(d, f)     asm("mov.b64 %0, {%1, %1};" : "=l"(d) : "f"(f))
#define UNPK2(lo, hi, d) asm("mov.b64 {%0, %1}, %2;" : "=f"(lo), "=f"(hi) : "l"(d))

// ---------------- kernels ----------------

__global__ void k_zero() {
    int i = blockIdx.x*1024 + threadIdx.x;
    ((double*)dg_sum)[i] = 0.0;
    ((double*)dg_ssq)[i] = 0.0;
}

// xx[b][n] = sum_d x^2
__global__ void k_xx(const float* __restrict__ x) {
    int b = blockIdx.x, n = threadIdx.x;
    float s = 0.f;
    #pragma unroll
    for (int d = 0; d < ND; d++) {
        float v = x[((size_t)b*ND + d)*NP + n];
        s = fmaf(v, v, s);
    }
    dg_xx[b*NP + n] = s;
}

// pd[b,n,m] = 2*dot(x_n,x_m) - xx_n - xx_m   (== -||x_n - x_m||^2)
// tile 32n x 32m, block (8,16)=128 threads, per-thread 2n x 4m packed FMA2
__global__ void __launch_bounds__(128) k_pdist(const float* __restrict__ x) {
    __shared__ float sn[ND][32], sm[ND][32];
    int b = blockIdx.z;
    int n0 = blockIdx.y*32, m0 = blockIdx.x*32;
    int tx = threadIdx.x, ty = threadIdx.y;
    int tid = ty*8 + tx;
    for (int e = tid; e < ND*32; e += 128) {
        int d = e >> 5, c = e & 31;
        size_t base = ((size_t)b*ND + d)*NP;
        sn[d][c] = x[base + n0 + c];
        sm[d][c] = x[base + m0 + c];
    }
    __syncthreads();
    ull acc[2][2] = {{0ull,0ull},{0ull,0ull}};
    #pragma unroll
    for (int d = 0; d < ND; d++) {
        ull sn2 = *(const ull*)&sn[d][ty*2];
        float nlo, nhi; UNPK2(nlo, nhi, sn2);
        ull dlo, dhi; DUP2(dlo, nlo); DUP2(dhi, nhi);
        ull mp0 = *(const ull*)&sm[d][tx*4];
        ull mp1 = *(const ull*)&sm[d][tx*4+2];
        FMA2(acc[0][0], mp0, dlo); FMA2(acc[0][1], mp1, dlo);
        FMA2(acc[1][0], mp0, dhi); FMA2(acc[1][1], mp1, dhi);
    }
    float xm[4];
    #pragma unroll
    for (int j = 0; j < 4; j++) xm[j] = dg_xx[b*NP + m0 + tx*4 + j];
    #pragma unroll
    for (int i = 0; i < 2; i++) {
        int n = n0 + ty*2 + i;
        float xn = dg_xx[b*NP + n];
        float v0, v1, v2, v3;
        UNPK2(v0, v1, acc[i][0]);
        UNPK2(v2, v3, acc[i][1]);
        float4 o = make_float4(2.f*v0 - xn - xm[0], 2.f*v1 - xn - xm[1],
                               2.f*v2 - xn - xm[2], 2.f*v3 - xn - xm[3]);
        *(float4*)(dg_pd + ((size_t)b*NP + n)*NP + m0 + tx*4) = o;
    }
}

// warp-per-row top-20: 1024 candidates held in registers (32/lane),
// iterative extraction with (value desc, index asc) — matches jax top_k set.
__global__ void k_topk() {
    int warp = threadIdx.x >> 5, lane = threadIdx.x & 31;
    int row = blockIdx.x*8 + warp;              // row = b*NP + n
    const float* rp = dg_pd + (size_t)row*NP;
    float v[32];
    #pragma unroll
    for (int i = 0; i < 8; i++) {
        float4 t = *(const float4*)(rp + i*128 + lane*4);
        v[i*4+0] = t.x; v[i*4+1] = t.y; v[i*4+2] = t.z; v[i*4+3] = t.w;
    }
    int* outp = dg_idx + (size_t)row*NK;
    for (int t = 0; t < NK; t++) {
        float best = v[0]; int bs = 0;
        #pragma unroll
        for (int s = 1; s < 32; s++) if (v[s] > best) { best = v[s]; bs = s; }
        int bi = ((bs >> 2) << 7) + (lane << 2) + (bs & 3);
        #pragma unroll
        for (int d = 16; d; d >>= 1) {
            float ov = __shfl_xor_sync(0xffffffffu, best, d);
            int   oi = __shfl_xor_sync(0xffffffffu, bi, d);
            if (ov > best || (ov == best && oi < bi)) { best = ov; bi = oi; }
        }
        if (lane == 0) outp[t] = bi;
        int wl = (bi >> 2) & 31;
        if (lane == wl) {
            int ws = ((bi >> 7) << 2) | (bi & 3);
            #pragma unroll
            for (int s = 0; s < 32; s++) if (s == ws) v[s] = -INFINITY;
        }
    }
}

// P[b,o,n] = w1a . x[:,n],  S[b,o,n] = (w1b - w1a) . x[:,n]
__global__ void k_ps(const float* __restrict__ x, const float* __restrict__ w1) {
    __shared__ float wa[ND], ws[ND];
    int o = blockIdx.y, b = blockIdx.z, tid = threadIdx.x;
    if (tid < ND) {
        float a = w1[o*120 + tid];
        wa[tid] = a;
        ws[tid] = w1[o*120 + 60 + tid] - a;
    }
    __syncthreads();
    int n = blockIdx.x*256 + tid;
    float p = 0.f, s = 0.f;
    #pragma unroll
    for (int d = 0; d < ND; d++) {
        float xv = x[((size_t)b*ND + d)*NP + n];
        p = fmaf(wa[d], xv, p);
        s = fmaf(ws[d], xv, s);
    }
    dg_P[((size_t)b*64 + o)*NP + n] = p;
    dg_S[((size_t)b*64 + o)*NP + n] = s;
}

// conv1 as gather + fused stats(stage0) + max -> z[0:64)
__global__ void k_h1(const float* __restrict__ b1) {
    int tid = threadIdx.x;
    int n = blockIdx.x*256 + tid;
    int o = blockIdx.y, b = blockIdx.z;
    float sv = dg_S[((size_t)b*64 + o)*NP + n] + b1[o];
    const float* Pb = dg_P + ((size_t)b*64 + o)*NP;
    const int* ip = dg_idx + ((size_t)b*NP + n)*NK;
    float vals[NK];
    float sum = 0.f, ss = 0.f, mx = -INFINITY;
    #pragma unroll
    for (int j = 0; j < NK; j++) {
        float v = Pb[ip[j]] + sv;
        vals[j] = v;
        sum += v;
        ss = fmaf(v, v, ss);
        mx = fmaxf(mx, v);
    }
    float* dst = dg_h1 + (((size_t)b*64 + o)*NP + n)*NK;
    #pragma unroll
    for (int j4 = 0; j4 < 5; j4++)
        ((float4*)dst)[j4] = make_float4(vals[4*j4], vals[4*j4+1], vals[4*j4+2], vals[4*j4+3]);
    dg_z[((size_t)b*512 + o)*NP + n] = mx;

    __shared__ float s1[256], s2[256];
    s1[tid] = sum; s2[tid] = ss;
    __syncthreads();
    for (int s = 128; s > 0; s >>= 1) {
        if (tid < s) { s1[tid] += s1[tid+s]; s2[tid] += s2[tid+s]; }
        __syncthreads();
    }
    if (tid == 0) {
        atomicAdd(&dg_sum[0][o], (double)s1[0]);
        atomicAdd(&dg_ssq[0][o], (double)s2[0]);
    }
}

__global__ void k_finalize(int stage, int C, float cnt,
                           const float* __restrict__ g, const float* __restrict__ be,
                           float* __restrict__ sc, float* __restrict__ sh) {
    int c = threadIdx.x;
    if (c < C) {
        double mu  = dg_sum[stage][c] / (double)cnt;
        double var = dg_ssq[stage][c] / (double)cnt - mu*mu;
        float scale = g[c] * (float)(1.0 / sqrt(var + 1e-5));
        sc[c] = scale;
        sh[c] = be[c] - (float)mu * scale;
    }
}

// ============ edge-domain SGEMM (FFMA2) with fused stats + max ============
// Tile (MI*16)m x 160t, 256 threads, per-thread MI x 5 f32x2-pairs.
template<int MI, bool WRITE>
__global__ void __launch_bounds__(256, 2) k_egemm(
        const float* __restrict__ A, const float* __restrict__ W,
        const float* __restrict__ bias,
        const float* __restrict__ sc, const float* __restrict__ sh,
        float* __restrict__ Out, int M, int K, int stage, int zoff) {
    __shared__ float As[16][160];
    __shared__ float Ws[16][MI*16 + 8];
    int b = blockIdx.z;
    const float* Ab = A + (size_t)b*K*NT;
    int m0 = blockIdx.y*(MI*16), t0 = blockIdx.x*160;
    int tid = threadIdx.x;
    int tx = tid & 15, ty = tid >> 4;
    ull acc[MI][5];
    #pragma unroll
    for (int i = 0; i < MI; i++)
        #pragma unroll
        for (int q = 0; q < 5; q++) acc[i][q] = 0ull;

    for (int k0 = 0; k0 < K; k0 += 16) {
        #pragma unroll
        for (int e = tid; e < 640; e += 256) {
            int r = e / 40, c = (e % 40) * 4;
            float4 v = *(const float4*)(Ab + (size_t)(k0+r)*NT + t0 + c);
            float s = sc[k0+r], h = sh[k0+r];
            v.x = fmaf(v.x, s, h); v.x = v.x >= 0.f ? v.x : SLOPE*v.x;
            v.y = fmaf(v.y, s, h); v.y = v.y >= 0.f ? v.y : SLOPE*v.y;
            v.z = fmaf(v.z, s, h); v.z = v.z >= 0.f ? v.z : SLOPE*v.z;
            v.w = fmaf(v.w, s, h); v.w = v.w >= 0.f ? v.w : SLOPE*v.w;
            *(float4*)&As[r][c] = v;
        }
        #pragma unroll
        for (int e = tid; e < MI*64; e += 256) {
            int r = e >> 2, c = (e & 3) * 4;
            float4 w = *(const float4*)(W + (size_t)(m0+r)*K + k0 + c);
            Ws[c+0][r] = w.x; Ws[c+1][r] = w.y; Ws[c+2][r] = w.z; Ws[c+3][r] = w.w;
        }
        __syncthreads();
        #pragma unroll
        for (int kk = 0; kk < 16; kk++) {
            const ull* arow = (const ull*)&As[kk][tx*10];
            ull ap[5];
            #pragma unroll
            for (int q = 0; q < 5; q++) ap[q] = arow[q];
            float wv[MI];
            #pragma unroll
            for (int h = 0; h < MI; h += 4) {
                float4 wf = *(const float4*)&Ws[kk][ty*MI + h];
                wv[h] = wf.x; wv[h+1] = wf.y; wv[h+2] = wf.z; wv[h+3] = wf.w;
            }
            #pragma unroll
            for (int i = 0; i < MI; i++) {
                ull wp; DUP2(wp, wv[i]);
                #pragma unroll
                for (int q = 0; q < 5; q++) FMA2(acc[i][q], ap[q], wp);
            }
        }
        __syncthreads();
    }

    float* Ob = WRITE ? (Out + (size_t)b*M*NT) : (float*)0;
    #pragma unroll
    for (int i = 0; i < MI; i++) {
        int m = m0 + ty*MI + i;
        float bv = bias[m];
        float sum = 0.f, ss = 0.f, mxv = -INFINITY;
        #pragma unroll
        for (int q = 0; q < 5; q++) {
            float lo, hi;
            UNPK2(lo, hi, acc[i][q]);
            lo += bv; hi += bv;
            if (WRITE)
                *(float2*)(Ob + (size_t)m*NT + t0 + tx*10 + 2*q) = make_float2(lo, hi);
            sum += lo + hi;
            ss = fmaf(lo, lo, ss); ss = fmaf(hi, hi, ss);
            mxv = fmaxf(mxv, fmaxf(lo, hi));
        }
        #pragma unroll
        for (int d = 1; d < 16; d <<= 1) {
            sum += __shfl_xor_sync(0xffffffffu, sum, d);
            ss  += __shfl_xor_sync(0xffffffffu, ss, d);
        }
        if (tx == 0) {
            atomicAdd(&dg_sum[stage][m], (double)sum);
            atomicAdd(&dg_ssq[stage][m], (double)ss);
        }
        float mo = fmaxf(mxv, __shfl_xor_sync(0xffffffffu, mxv, 1));
        if ((tx & 1) == 0)
            dg_z[((size_t)b*512 + zoff + m)*NP + blockIdx.x*8 + (tx >> 1)] = mo;
    }
}

// ============ point-domain SGEMM (FFMA2) with fused stats ============
// Tile (MI*16)m x 128t, 256 threads, per-thread MI x 4 f32x2-pairs.
template<int MI>
__global__ void __launch_bounds__(256, 2) k_pgemm(
        const float* __restrict__ A, const float* __restrict__ W,
        const float* __restrict__ bias,
        const float* __restrict__ sc, const float* __restrict__ sh,
        float* __restrict__ Out, int M, int K, int stage) {
    __shared__ float As[16][128];
    __shared__ float Ws[16][MI*16 + 8];
    int b = blockIdx.z;
    const float* Ab = A + (size_t)b*K*NP;
    float* Ob = Out + (size_t)b*M*NP;
    int m0 = blockIdx.y*(MI*16), t0 = blockIdx.x*128;
    int tid = threadIdx.x;
    int tx = tid & 15, ty = tid >> 4;
    ull acc[MI][4];
    #pragma unroll
    for (int i = 0; i < MI; i++)
        #pragma unroll
        for (int q = 0; q < 4; q++) acc[i][q] = 0ull;

    for (int k0 = 0; k0 < K; k0 += 16) {
        #pragma unroll
        for (int e = tid; e < 512; e += 256) {
            int r = e >> 5, c = (e & 31) * 4;
            float4 v = *(const float4*)(Ab + (size_t)(k0+r)*NP + t0 + c);
            float s = sc[k0+r], h = sh[k0+r];
            v.x = fmaf(v.x, s, h); v.x = v.x >= 0.f ? v.x : SLOPE*v.x;
            v.y = fmaf(v.y, s, h); v.y = v.y >= 0.f ? v.y : SLOPE*v.y;
            v.z = fmaf(v.z, s, h); v.z = v.z >= 0.f ? v.z : SLOPE*v.z;
            v.w = fmaf(v.w, s, h); v.w = v.w >= 0.f ? v.w : SLOPE*v.w;
            *(float4*)&As[r][c] = v;
        }
        #pragma unroll
        for (int e = tid; e < MI*64; e += 256) {
            int r = e >> 2, c = (e & 3) * 4;
            float4 w = *(const float4*)(W + (size_t)(m0+r)*K + k0 + c);
            Ws[c+0][r] = w.x; Ws[c+1][r] = w.y; Ws[c+2][r] = w.z; Ws[c+3][r] = w.w;
        }
        __syncthreads();
        #pragma unroll
        for (int kk = 0; kk < 16; kk++) {
            const ull* arow = (const ull*)&As[kk][0];
            ull ap[4];
            #pragma unroll
            for (int q = 0; q < 4; q++) ap[q] = arow[tx + 16*q];
            float wv[MI];
            #pragma unroll
            for (int h = 0; h < MI; h += 4) {
                float4 wf = *(const float4*)&Ws[kk][ty*MI + h];
                wv[h] = wf.x; wv[h+1] = wf.y; wv[h+2] = wf.z; wv[h+3] = wf.w;
            }
            #pragma unroll
            for (int i = 0; i < MI; i++) {
                ull wp; DUP2(wp, wv[i]);
                #pragma unroll
                for (int q = 0; q < 4; q++) FMA2(acc[i][q], ap[q], wp);
            }
        }
        __syncthreads();
    }

    #pragma unroll
    for (int i = 0; i < MI; i++) {
        int m = m0 + ty*MI + i;
        float bv = bias[m];
        float sum = 0.f, ss = 0.f;
        #pragma unroll
        for (int q = 0; q < 4; q++) {
            float lo, hi;
            UNPK2(lo, hi, acc[i][q]);
            lo += bv; hi += bv;
            *(float2*)(Ob + (size_t)m*NP + t0 + 2*tx + 32*q) = make_float2(lo, hi);
            sum += lo + hi;
            ss = fmaf(lo, lo, ss); ss = fmaf(hi, hi, ss);
        }
        #pragma unroll
        for (int d = 1; d < 16; d <<= 1) {
            sum += __shfl_xor_sync(0xffffffffu, sum, d);
            ss  += __shfl_xor_sync(0xffffffffu, ss, d);
        }
        if (tx == 0) {
            atomicAdd(&dg_sum[stage][m], (double)sum);
            atomicAdd(&dg_ssq[stage][m], (double)ss);
        }
    }
}

// final bn+lrelu + (B,C,N) -> (B,N,C) transpose
__global__ void k_out(float* __restrict__ out) {
    __shared__ float st[32][33];
    int b = blockIdx.z;
    int c0 = blockIdx.y*32, n0 = blockIdx.x*32;
    int tx = threadIdx.x, ty = threadIdx.y;
    int c = c0 + ty;
    float v = dg_o6[((size_t)b*1024 + c)*NP + n0 + tx];
    v = fmaf(v, dg_sc6[c], dg_sh6[c]);
    st[ty][tx] = v >= 0.f ? v : SLOPE*v;
    __syncthreads();
    out[((size_t)b*NP + n0 + ty)*1024 + c0 + tx] = st[tx][ty];
}

// ---------------- host orchestration ----------------

extern "C" void kernel_launch(void* const* d_in, const int* in_sizes, int n_in,
                              void* d_out, int out_size) {
    (void)in_sizes; (void)n_in; (void)out_size;
    const float* x  = (const float*)d_in[0];
    const float* w1 = (const float*)d_in[1];
    const float* b1 = (const float*)d_in[2];
    const float* g1 = (const float*)d_in[3];
    const float* be1= (const float*)d_in[4];
    const float* w2 = (const float*)d_in[5];
    const float* b2 = (const float*)d_in[6];
    const float* g2 = (const float*)d_in[7];
    const float* be2= (const float*)d_in[8];
    const float* w3 = (const float*)d_in[9];
    const float* b3 = (const float*)d_in[10];
    const float* g3 = (const float*)d_in[11];
    const float* be3= (const float*)d_in[12];
    const float* w4 = (const float*)d_in[13];
    const float* b4 = (const float*)d_in[14];
    const float* g4 = (const float*)d_in[15];
    const float* be4= (const float*)d_in[16];
    const float* w5 = (const float*)d_in[17];
    const float* b5 = (const float*)d_in[18];
    const float* g5 = (const float*)d_in[19];
    const float* be5= (const float*)d_in[20];
    const float* w6 = (const float*)d_in[21];
    const float* b6 = (const float*)d_in[22];
    const float* g6 = (const float*)d_in[23];
    const float* be6= (const float*)d_in[24];

    float *p_h1, *p_h2, *p_h3, *p_z, *p_o5, *p_o6;
    float *p_scZ, *p_shZ, *p_sc5, *p_sh5, *p_sc6, *p_sh6;
    cudaGetSymbolAddress((void**)&p_h1, dg_h1);
    cudaGetSymbolAddress((void**)&p_h2, dg_h2);
    cudaGetSymbolAddress((void**)&p_h3, dg_h3);
    cudaGetSymbolAddress((void**)&p_z,  dg_z);
    cudaGetSymbolAddress((void**)&p_o5, dg_o5);
    cudaGetSymbolAddress((void**)&p_o6, dg_o6);
    cudaGetSymbolAddress((void**)&p_scZ, dg_scZ);
    cudaGetSymbolAddress((void**)&p_shZ, dg_shZ);
    cudaGetSymbolAddress((void**)&p_sc5, dg_sc5);
    cudaGetSymbolAddress((void**)&p_sh5, dg_sh5);
    cudaGetSymbolAddress((void**)&p_sc6, dg_sc6);
    cudaGetSymbolAddress((void**)&p_sh6, dg_sh6);

    const float cntE = (float)(NB*NP*NK);
    const float cntP = (float)(NB*NP);

    k_zero<<<6, 1024>>>();
    k_xx<<<NB, NP>>>(x);
    k_pdist<<<dim3(NP/32, NP/32, NB), dim3(8, 16)>>>(x);
    k_topk<<<NB*NP/8, 256>>>();
    k_ps<<<dim3(NP/256, 64, NB), 256>>>(x, w1);

    k_h1<<<dim3(NP/256, 64, NB), 256>>>(b1);
    k_finalize<<<1, 64>>>(0, 64, cntE, g1, be1, p_scZ, p_shZ);

    // conv2: 64 <- 64 (M tile 64, MI=4)
    k_egemm<4, true><<<dim3(NT/160, 1, NB), 256>>>(p_h1, w2, b2, p_scZ, p_shZ, p_h2, 64, 64, 1, 64);
    k_finalize<<<1, 64>>>(1, 64, cntE, g2, be2, p_scZ + 64, p_shZ + 64);

    // conv3: 128 <- 64 (M tile 128, MI=8)
    k_egemm<8, true><<<dim3(NT/160, 1, NB), 256>>>(p_h2, w3, b3, p_scZ + 64, p_shZ + 64, p_h3, 128, 64, 2, 128);
    k_finalize<<<1, 128>>>(2, 128, cntE, g3, be3, p_scZ + 128, p_shZ + 128);

    // conv4: 256 <- 128, no output tensor (stats+max only)
    k_egemm<8, false><<<dim3(NT/160, 2, NB), 256>>>(p_h3, w4, b4, p_scZ + 128, p_shZ + 128, (float*)0, 256, 128, 3, 256);
    k_finalize<<<1, 256>>>(3, 256, cntE, g4, be4, p_scZ + 256, p_shZ + 256);

    // conv5: 256 <- 512 over points
    k_pgemm<8><<<dim3(NP/128, 2, NB), 256>>>(p_z, w5, b5, p_scZ, p_shZ, p_o5, 256, 512, 4);
    k_finalize<<<1, 256>>>(4, 256, cntP, g5, be5, p_sc5, p_sh5);

    // conv6: 1024 <- 256
    k_pgemm<8><<<dim3(NP/128, 8, NB), 256>>>(p_o5, w6, b6, p_sc5, p_sh5, p_o6, 1024, 256, 5);
    k_finalize<<<1, 1024>>>(5, 1024, cntP, g6, be6, p_sc6, p_sh6);

    k_out<<<dim3(NP/32, 1024/32, NB), dim3(32, 32)>>>((float*)d_out);
}